// round 5
// baseline (speedup 1.0000x reference)
#include <cuda_runtime.h>
#include <cstdint>
#include <math.h>

#define SEQ  2048
#define DM   1024
#define NH   16
#define HD   64
#define DFF  4096

// ---------------- scratch (no allocation allowed) ----------------
__device__ float g_normed [SEQ * DM];
__device__ float g_qkv    [SEQ * 3 * DM];
__device__ float g_q      [NH * SEQ * HD];
__device__ float g_k      [NH * SEQ * HD];
__device__ float g_v      [NH * SEQ * HD];
__device__ float g_attn   [SEQ * DM];
__device__ float g_x2     [SEQ * DM];
__device__ float g_normed2[SEQ * DM];
__device__ float g_ffh    [SEQ * DFF];
// tf32-pre-rounded weight copies
__device__ float g_wqkv_t [DM * 3 * DM];
__device__ float g_wout_t [DM * DM];
__device__ float g_wff1_t [DM * DFF];
__device__ float g_wff2_t [DFF * DM];

// ---------------- tf32 helpers ----------------
__device__ __forceinline__ float tf32r(float x) {
    float y;
    asm("cvt.rna.tf32.f32 %0, %1;" : "=f"(y) : "f"(x));
    return y;
}
__device__ __forceinline__ float4 cvt4(float4 v) {
    v.x = tf32r(v.x); v.y = tf32r(v.y); v.z = tf32r(v.z); v.w = tf32r(v.w);
    return v;
}
__device__ __forceinline__ void mma8(float* d, const float* a, const float* b) {
    asm volatile(
        "mma.sync.aligned.m16n8k8.row.col.f32.tf32.tf32.f32 "
        "{%0,%1,%2,%3}, {%4,%5,%6,%7}, {%8,%9}, {%0,%1,%2,%3};\n"
        : "+f"(d[0]), "+f"(d[1]), "+f"(d[2]), "+f"(d[3])
        : "r"(__float_as_uint(a[0])), "r"(__float_as_uint(a[1])),
          "r"(__float_as_uint(a[2])), "r"(__float_as_uint(a[3])),
          "r"(__float_as_uint(b[0])), "r"(__float_as_uint(b[1])));
}
__device__ __forceinline__ void cp16(void* sdst, const void* gsrc) {
    unsigned int d = (unsigned int)__cvta_generic_to_shared(sdst);
    asm volatile("cp.async.cg.shared.global [%0], [%1], 16;\n" :: "r"(d), "l"(gsrc));
}

// ---------------- weight pre-round kernel ----------------
__global__ __launch_bounds__(256) void tf32_round_kernel(
    const float* __restrict__ src, float* __restrict__ dst, int n4)
{
    int i = blockIdx.x * blockDim.x + threadIdx.x;
    int stride = gridDim.x * blockDim.x;
    for (; i < n4; i += stride) {
        float4 v = reinterpret_cast<const float4*>(src)[i];
        reinterpret_cast<float4*>(dst)[i] = cvt4(v);
    }
}

// ---------------- LayerNorm (rounds output to tf32: feeds GEMM A only) --------
__global__ __launch_bounds__(256) void ln_kernel(
    const float* __restrict__ x, const float* __restrict__ g,
    const float* __restrict__ b, float* __restrict__ out)
{
    int row = blockIdx.x;
    int tid = threadIdx.x;
    const float* xr = x + (size_t)row * DM;
    float4 xv = reinterpret_cast<const float4*>(xr)[tid];
    float s  = xv.x + xv.y + xv.z + xv.w;
    float sq = xv.x*xv.x + xv.y*xv.y + xv.z*xv.z + xv.w*xv.w;

    __shared__ float sh1[256], sh2[256];
    sh1[tid] = s; sh2[tid] = sq;
    __syncthreads();
    #pragma unroll
    for (int o = 128; o > 0; o >>= 1) {
        if (tid < o) { sh1[tid] += sh1[tid + o]; sh2[tid] += sh2[tid + o]; }
        __syncthreads();
    }
    float mu   = sh1[0] * (1.0f / DM);
    float var  = sh2[0] * (1.0f / DM) - mu * mu;
    float rstd = rsqrtf(var + 1e-5f);

    float4 gv = reinterpret_cast<const float4*>(g)[tid];
    float4 bv = reinterpret_cast<const float4*>(b)[tid];
    float4 o4;
    o4.x = tf32r((xv.x - mu) * rstd * gv.x + bv.x);
    o4.y = tf32r((xv.y - mu) * rstd * gv.y + bv.y);
    o4.z = tf32r((xv.z - mu) * rstd * gv.z + bv.z);
    o4.w = tf32r((xv.w - mu) * rstd * gv.w + bv.w);
    reinterpret_cast<float4*>(out + (size_t)row * DM)[tid] = o4;
}

// ---------------- tf32 MMA GEMM v2: 128x128 block, 4 warps, 64x64 warp tile ----
// 4-stage cp.async pipeline, BK=16. Inputs A,B must be pre-rounded to tf32.
// OP = 0: C = A*B + bias
// OP = 1: C = A*B + bias + res            (fp32 output)
// OP = 2: C = tf32r(gelu(A*B + bias))     (feeds next GEMM A)
#define ASTRIDE 20
#define BSTRIDE 136
#define STAGE_F (128 * ASTRIDE + 16 * BSTRIDE)
#define NSTAGE  4

template<int OP>
__global__ __launch_bounds__(128) void mma_gemm2(
    const float* __restrict__ A, const float* __restrict__ B,
    const float* __restrict__ bias, const float* __restrict__ res,
    float* __restrict__ C, int M, int N, int K)
{
    extern __shared__ float sm[];

    const int tid  = threadIdx.x;
    const int lane = tid & 31;
    const int warp = tid >> 5;
    const int g    = lane >> 2;
    const int tig  = lane & 3;
    const int wm   = warp >> 1;      // 0..1
    const int wn   = warp & 1;       // 0..1
    const int m0   = blockIdx.y * 128;
    const int n0   = blockIdx.x * 128;

    // per-thread cp.async coords
    const int ar = tid >> 2;              // A row (0..31, +32k)
    const int ak = (tid & 3) * 4;         // A k-chunk
    const int br = tid >> 5;              // B row (0..3, +4k)
    const int bn = (tid & 31) * 4;        // B col chunk

    float acc[4][8][4];
    #pragma unroll
    for (int mt = 0; mt < 4; mt++)
        #pragma unroll
        for (int nt = 0; nt < 8; nt++)
            #pragma unroll
            for (int i = 0; i < 4; i++) acc[mt][nt][i] = 0.0f;

    const int nsteps = K >> 4;

    // prologue: stages 0..2
    #pragma unroll
    for (int s = 0; s < NSTAGE - 1; s++) {
        float* As = sm + s * STAGE_F;
        float* Bs = As + 128 * ASTRIDE;
        #pragma unroll
        for (int i = 0; i < 4; i++) {
            int row = ar + i * 32;
            cp16(&As[row * ASTRIDE + ak], A + (size_t)(m0 + row) * K + s * 16 + ak);
        }
        #pragma unroll
        for (int i = 0; i < 4; i++) {
            int row = br + i * 4;
            cp16(&Bs[row * BSTRIDE + bn], B + (size_t)(s * 16 + row) * N + n0 + bn);
        }
        asm volatile("cp.async.commit_group;\n");
    }

    for (int it = 0; it < nsteps; it++) {
        asm volatile("cp.async.wait_group 2;\n");
        __syncthreads();

        // prefetch stage it+3
        if (it + NSTAGE - 1 < nsteps) {
            const int s  = (it + NSTAGE - 1) & (NSTAGE - 1);
            const int kt = (it + NSTAGE - 1) * 16;
            float* As = sm + s * STAGE_F;
            float* Bs = As + 128 * ASTRIDE;
            #pragma unroll
            for (int i = 0; i < 4; i++) {
                int row = ar + i * 32;
                cp16(&As[row * ASTRIDE + ak], A + (size_t)(m0 + row) * K + kt + ak);
            }
            #pragma unroll
            for (int i = 0; i < 4; i++) {
                int row = br + i * 4;
                cp16(&Bs[row * BSTRIDE + bn], B + (size_t)(kt + row) * N + n0 + bn);
            }
        }
        asm volatile("cp.async.commit_group;\n");

        const float* As = sm + (it & (NSTAGE - 1)) * STAGE_F;
        const float* Bs = As + 128 * ASTRIDE;

        #pragma unroll
        for (int kb = 0; kb < 16; kb += 8) {
            float a[4][4], b[8][2];
            #pragma unroll
            for (int mt = 0; mt < 4; mt++) {
                const int r = wm * 64 + mt * 16;
                a[mt][0] = As[(r + g)     * ASTRIDE + kb + tig];
                a[mt][1] = As[(r + 8 + g) * ASTRIDE + kb + tig];
                a[mt][2] = As[(r + g)     * ASTRIDE + kb + tig + 4];
                a[mt][3] = As[(r + 8 + g) * ASTRIDE + kb + tig + 4];
            }
            #pragma unroll
            for (int nt = 0; nt < 8; nt++) {
                const int c = wn * 64 + nt * 8 + g;
                b[nt][0] = Bs[(kb + tig)     * BSTRIDE + c];
                b[nt][1] = Bs[(kb + tig + 4) * BSTRIDE + c];
            }
            #pragma unroll
            for (int mt = 0; mt < 4; mt++)
                #pragma unroll
                for (int nt = 0; nt < 8; nt++)
                    mma8(acc[mt][nt], a[mt], b[nt]);
        }
    }

    // epilogue
    #pragma unroll
    for (int mt = 0; mt < 4; mt++) {
        const int r0 = m0 + wm * 64 + mt * 16 + g;
        const int r1 = r0 + 8;
        #pragma unroll
        for (int nt = 0; nt < 8; nt++) {
            const int c = n0 + wn * 64 + nt * 8 + tig * 2;
            const float b0 = bias[c], b1 = bias[c + 1];
            float v0 = acc[mt][nt][0] + b0;
            float v1 = acc[mt][nt][1] + b1;
            float v2 = acc[mt][nt][2] + b0;
            float v3 = acc[mt][nt][3] + b1;
            if (OP == 1) {
                const float2 ra = *reinterpret_cast<const float2*>(res + (size_t)r0 * N + c);
                const float2 rb = *reinterpret_cast<const float2*>(res + (size_t)r1 * N + c);
                v0 += ra.x; v1 += ra.y; v2 += rb.x; v3 += rb.y;
            }
            if (OP == 2) {
                v0 = tf32r(0.5f * v0 * (1.0f + erff(v0 * 0.70710678118654752f)));
                v1 = tf32r(0.5f * v1 * (1.0f + erff(v1 * 0.70710678118654752f)));
                v2 = tf32r(0.5f * v2 * (1.0f + erff(v2 * 0.70710678118654752f)));
                v3 = tf32r(0.5f * v3 * (1.0f + erff(v3 * 0.70710678118654752f)));
            }
            *reinterpret_cast<float2*>(C + (size_t)r0 * N + c) = make_float2(v0, v1);
            *reinterpret_cast<float2*>(C + (size_t)r1 * N + c) = make_float2(v2, v3);
        }
    }
}

// ---------------- split qkv, L2-normalize q,k; relayout to [H,L,64] --
__global__ __launch_bounds__(256) void qkvnorm_kernel(
    const float* __restrict__ qkv, float* __restrict__ Q,
    float* __restrict__ Km, float* __restrict__ V)
{
    int gw   = (blockIdx.x * blockDim.x + threadIdx.x) >> 5;
    int lane = threadIdx.x & 31;
    int l = gw >> 4;
    int h = gw & 15;

    const float* base = qkv + (size_t)l * (3 * DM);
    size_t oidx = ((size_t)h * SEQ + l) * HD + lane * 2;

    float2 qv = *reinterpret_cast<const float2*>(base + h * HD + lane * 2);
    float ssq = qv.x * qv.x + qv.y * qv.y;
    #pragma unroll
    for (int o = 16; o > 0; o >>= 1) ssq += __shfl_xor_sync(0xffffffffu, ssq, o);
    float scq = 0.125f / fmaxf(sqrtf(ssq), 1e-12f);
    *reinterpret_cast<float2*>(Q + oidx) = make_float2(qv.x * scq, qv.y * scq);

    float2 kv = *reinterpret_cast<const float2*>(base + DM + h * HD + lane * 2);
    float ssk = kv.x * kv.x + kv.y * kv.y;
    #pragma unroll
    for (int o = 16; o > 0; o >>= 1) ssk += __shfl_xor_sync(0xffffffffu, ssk, o);
    float sck = 1.0f / fmaxf(sqrtf(ssk), 1e-12f);
    *reinterpret_cast<float2*>(Km + oidx) = make_float2(kv.x * sck, kv.y * sck);

    float2 vv = *reinterpret_cast<const float2*>(base + 2 * DM + h * HD + lane * 2);
    *reinterpret_cast<float2*>(V + oidx) = vv;
}

// ---------------- MMA attention (rounds output: feeds out-proj GEMM A) --------
#define APAD 68
__global__ __launch_bounds__(256) void attn_mma_kernel(
    const float* __restrict__ Q, const float* __restrict__ Km,
    const float* __restrict__ V, const float* __restrict__ lcc,
    float* __restrict__ out)
{
    __shared__ __align__(16) float pool[128 * APAD];
    __shared__ float lccs[64];
    float* Qs = pool;
    float* Ks = pool;
    float* Vs = pool + 64 * APAD;

    const int h    = blockIdx.y;
    const int m0   = blockIdx.x * 128;
    const int tid  = threadIdx.x;
    const int lane = tid & 31;
    const int warp = tid >> 5;
    const int g    = lane >> 2;
    const int tig  = lane & 3;

    {
        const float* Qg = Q + ((size_t)h * SEQ + m0) * HD;
        #pragma unroll
        for (int t = 0; t < 8; t++) {
            int idx = t * 256 + tid;
            int row = idx >> 4;
            int c4  = (idx & 15) * 4;
            float4 v = *reinterpret_cast<const float4*>(Qg + (size_t)row * HD + c4);
            *reinterpret_cast<float4*>(&Qs[row * APAD + c4]) = cvt4(v);
        }
    }
    __syncthreads();

    float qa[8][4];
    {
        const int r = warp * 16;
        #pragma unroll
        for (int kc = 0; kc < 8; kc++) {
            qa[kc][0] = Qs[(r + g)     * APAD + kc * 8 + tig];
            qa[kc][1] = Qs[(r + 8 + g) * APAD + kc * 8 + tig];
            qa[kc][2] = Qs[(r + g)     * APAD + kc * 8 + tig + 4];
            qa[kc][3] = Qs[(r + 8 + g) * APAD + kc * 8 + tig + 4];
        }
    }

    const float rb0 = lcc[m0 + warp * 16 + g]     * 0.05f;
    const float rb1 = lcc[m0 + warp * 16 + 8 + g] * 0.05f;

    float o[8][4];
    #pragma unroll
    for (int nt = 0; nt < 8; nt++)
        #pragma unroll
        for (int i = 0; i < 4; i++) o[nt][i] = 0.0f;
    float d0 = 0.0f, d1 = 0.0f;

    const int src0 = (g << 2) | (tig >> 1);
    const int src1 = src0 + 2;
    const bool odd = (tig & 1);

    for (int kt = 0; kt < SEQ; kt += 64) {
        __syncthreads();
        {
            const float* Kg = Km + ((size_t)h * SEQ + kt) * HD;
            const float* Vg = V  + ((size_t)h * SEQ + kt) * HD;
            int row = tid >> 4;
            int c4  = (tid & 15) * 4;
            #pragma unroll
            for (int t = 0; t < 4; t++) {
                int r = row + t * 16;
                float4 kv = *reinterpret_cast<const float4*>(Kg + (size_t)r * HD + c4);
                float4 vv = *reinterpret_cast<const float4*>(Vg + (size_t)r * HD + c4);
                *reinterpret_cast<float4*>(&Ks[r * APAD + c4]) = cvt4(kv);
                *reinterpret_cast<float4*>(&Vs[r * APAD + c4]) = cvt4(vv);
            }
            if (tid < 64) lccs[tid] = lcc[kt + tid] * 0.05f;
        }
        __syncthreads();

        float s[8][4];
        #pragma unroll
        for (int nt = 0; nt < 8; nt++)
            #pragma unroll
            for (int i = 0; i < 4; i++) s[nt][i] = 0.0f;

        #pragma unroll
        for (int kc = 0; kc < 8; kc++) {
            #pragma unroll
            for (int nt = 0; nt < 8; nt++) {
                float b[2];
                b[0] = Ks[(nt * 8 + g) * APAD + kc * 8 + tig];
                b[1] = Ks[(nt * 8 + g) * APAD + kc * 8 + tig + 4];
                mma8(s[nt], qa[kc], b);
            }
        }

        #pragma unroll
        for (int nt = 0; nt < 8; nt++) {
            float cb0 = lccs[nt * 8 + tig * 2];
            float cb1 = lccs[nt * 8 + tig * 2 + 1];
            float v0 = s[nt][0] + rb0 + cb0;
            float v1 = s[nt][1] + rb0 + cb1;
            float v2 = s[nt][2] + rb1 + cb0;
            float v3 = s[nt][3] + rb1 + cb1;
            v0 = fminf(10.0f, fmaxf(-10.0f, v0));
            v1 = fminf(10.0f, fmaxf(-10.0f, v1));
            v2 = fminf(10.0f, fmaxf(-10.0f, v2));
            v3 = fminf(10.0f, fmaxf(-10.0f, v3));
            float p0 = tf32r(__expf(v0));
            float p1 = tf32r(__expf(v1));
            float p2 = tf32r(__expf(v2));
            float p3 = tf32r(__expf(v3));
            s[nt][0] = p0; s[nt][1] = p1; s[nt][2] = p2; s[nt][3] = p3;
            d0 += p0 + p1;
            d1 += p2 + p3;
        }

        #pragma unroll
        for (int kc = 0; kc < 8; kc++) {
            float t00 = __shfl_sync(0xffffffffu, s[kc][0], src0);
            float t01 = __shfl_sync(0xffffffffu, s[kc][1], src0);
            float t02 = __shfl_sync(0xffffffffu, s[kc][2], src0);
            float t03 = __shfl_sync(0xffffffffu, s[kc][3], src0);
            float t10 = __shfl_sync(0xffffffffu, s[kc][0], src1);
            float t11 = __shfl_sync(0xffffffffu, s[kc][1], src1);
            float t12 = __shfl_sync(0xffffffffu, s[kc][2], src1);
            float t13 = __shfl_sync(0xffffffffu, s[kc][3], src1);
            float a[4];
            a[0] = odd ? t01 : t00;
            a[1] = odd ? t03 : t02;
            a[2] = odd ? t11 : t10;
            a[3] = odd ? t13 : t12;
            #pragma unroll
            for (int nt = 0; nt < 8; nt++) {
                float b[2];
                b[0] = Vs[(kc * 8 + tig)     * APAD + nt * 8 + g];
                b[1] = Vs[(kc * 8 + tig + 4) * APAD + nt * 8 + g];
                mma8(o[nt], a, b);
            }
        }
    }

    d0 += __shfl_xor_sync(0xffffffffu, d0, 1);
    d0 += __shfl_xor_sync(0xffffffffu, d0, 2);
    d1 += __shfl_xor_sync(0xffffffffu, d1, 1);
    d1 += __shfl_xor_sync(0xffffffffu, d1, 2);
    const float inv0 = 1.0f / d0;
    const float inv1 = 1.0f / d1;

    const int r0 = m0 + warp * 16 + g;
    const int r1 = r0 + 8;
    #pragma unroll
    for (int nt = 0; nt < 8; nt++) {
        const int c = h * HD + nt * 8 + tig * 2;
        *reinterpret_cast<float2*>(out + (size_t)r0 * DM + c) =
            make_float2(tf32r(o[nt][0] * inv0), tf32r(o[nt][1] * inv0));
        *reinterpret_cast<float2*>(out + (size_t)r1 * DM + c) =
            make_float2(tf32r(o[nt][2] * inv1), tf32r(o[nt][3] * inv1));
    }
}

// ---------------- launch --------------------------------------------------------
extern "C" void kernel_launch(void* const* d_in, const int* in_sizes, int n_in,
                              void* d_out, int out_size)
{
    const float* x     = (const float*)d_in[0];
    const float* lcc   = (const float*)d_in[1];
    const float* w_qkv = (const float*)d_in[2];
    const float* b_qkv = (const float*)d_in[3];
    const float* w_out = (const float*)d_in[4];
    const float* b_out = (const float*)d_in[5];
    const float* ln1_g = (const float*)d_in[6];
    const float* ln1_b = (const float*)d_in[7];
    const float* ln2_g = (const float*)d_in[8];
    const float* ln2_b = (const float*)d_in[9];
    const float* w_ff1 = (const float*)d_in[10];
    const float* b_ff1 = (const float*)d_in[11];
    const float* w_ff2 = (const float*)d_in[12];
    const float* b_ff2 = (const float*)d_in[13];
    float* out = (float*)d_out;

    float *normed, *qkv, *q, *k, *v, *attn, *x2, *normed2, *ffh;
    float *wqkv_t, *wout_t, *wff1_t, *wff2_t;
    cudaGetSymbolAddress((void**)&normed,  g_normed);
    cudaGetSymbolAddress((void**)&qkv,     g_qkv);
    cudaGetSymbolAddress((void**)&q,       g_q);
    cudaGetSymbolAddress((void**)&k,       g_k);
    cudaGetSymbolAddress((void**)&v,       g_v);
    cudaGetSymbolAddress((void**)&attn,    g_attn);
    cudaGetSymbolAddress((void**)&x2,      g_x2);
    cudaGetSymbolAddress((void**)&normed2, g_normed2);
    cudaGetSymbolAddress((void**)&ffh,     g_ffh);
    cudaGetSymbolAddress((void**)&wqkv_t,  g_wqkv_t);
    cudaGetSymbolAddress((void**)&wout_t,  g_wout_t);
    cudaGetSymbolAddress((void**)&wff1_t,  g_wff1_t);
    cudaGetSymbolAddress((void**)&wff2_t,  g_wff2_t);

    const int smem = NSTAGE * STAGE_F * 4;
    cudaFuncSetAttribute(mma_gemm2<0>, cudaFuncAttributeMaxDynamicSharedMemorySize, smem);
    cudaFuncSetAttribute(mma_gemm2<1>, cudaFuncAttributeMaxDynamicSharedMemorySize, smem);
    cudaFuncSetAttribute(mma_gemm2<2>, cudaFuncAttributeMaxDynamicSharedMemorySize, smem);

    // 0. pre-round weights to tf32
    tf32_round_kernel<<<512, 256>>>(w_qkv, wqkv_t, DM * 3 * DM / 4);
    tf32_round_kernel<<<256, 256>>>(w_out, wout_t, DM * DM / 4);
    tf32_round_kernel<<<512, 256>>>(w_ff1, wff1_t, DM * DFF / 4);
    tf32_round_kernel<<<512, 256>>>(w_ff2, wff2_t, DFF * DM / 4);

    // 1. LN1 (tf32-rounded output)
    ln_kernel<<<SEQ, 256>>>(x, ln1_g, ln1_b, normed);
    // 2. QKV projection
    mma_gemm2<0><<<dim3(3 * DM / 128, SEQ / 128), 128, smem>>>(
        normed, wqkv_t, b_qkv, nullptr, qkv, SEQ, 3 * DM, DM);
    // 3. split + cosine-normalize + relayout
    qkvnorm_kernel<<<(SEQ * NH * 32) / 256, 256>>>(qkv, q, k, v);
    // 4. attention (tf32 MMA, rounded output)
    attn_mma_kernel<<<dim3(SEQ / 128, NH), 256>>>(q, k, v, lcc, attn);
    // 5. out projection + residual (fp32 out)
    mma_gemm2<1><<<dim3(DM / 128, SEQ / 128), 128, smem>>>(
        attn, wout_t, b_out, x, x2, SEQ, DM, DM);
    // 6. LN2 (tf32-rounded output)
    ln_kernel<<<SEQ, 256>>>(x2, ln2_g, ln2_b, normed2);
    // 7. FF1 + exact GELU (tf32-rounded output)
    mma_gemm2<2><<<dim3(DFF / 128, SEQ / 128), 128, smem>>>(
        normed2, wff1_t, b_ff1, nullptr, ffh, SEQ, DFF, DM);
    // 8. FF2 + residual -> out (fp32)
    mma_gemm2<1><<<dim3(DM / 128, SEQ / 128), 128, smem>>>(
        ffh, wff2_t, b_ff2, x2, out, SEQ, DM, DFF);
}